// round 17
// baseline (speedup 1.0000x reference)
#include <cuda_runtime.h>
#include <cstdint>

#define B 8192
#define TC 128                 // tile cols (warp = 32 lanes x float4)
#define TR 128                 // tile rows (smaller: s_part fits 8 blocks/SM)
#define GX (B / TC)            // 64
#define GY (B / TR)            // 64
#define K2_BLOCKS 64

#define NEG_INF __int_as_float(0xff800000)
#define ENC_OFF 0x007FFFFFu    // shifted so enc2(-inf) == 0 (zero-init scratch)

// Final max arrays (zero-init == enc(-inf); K2 resets them after reading).
__device__ unsigned g_rowmax[B];         // 32 KB
__device__ unsigned g_colmax[B];         // 32 KB
__device__ float    g_diag[B];
__device__ float    g_blocksum[K2_BLOCKS];
__device__ unsigned g_done;              // zero-init; reset by K2 finisher

// Monotone float<->uint encoding (shifted): atomicMax(unsigned) == float max.
__device__ __forceinline__ unsigned enc2(float f) {
    unsigned u = __float_as_uint(f);
    return (u ^ ((unsigned)((int)u >> 31) | 0x80000000u)) - ENC_OFF;
}
__device__ __forceinline__ float dec2(unsigned e) {
    unsigned x = e + ENC_OFF;
    unsigned u = (x & 0x80000000u) ? (x ^ 0x80000000u) : ~x;
    return __uint_as_float(u);
}

// ---------------------------------------------------------------------------
// K1: hot loop with ZERO warp collectives. Per-lane row partials go to
// padded shared (conflict-free); the cross-lane reduction happens once at
// drain. Loads stay front-batched (4 independent LDG.128 per warp batch).
// ---------------------------------------------------------------------------
template<bool DIAG>
__device__ __forceinline__ void scan_body(const float* __restrict__ sim,
                                          int rowBase, int colBase,
                                          int tx, int ty, float* cm,
                                          float* s_part /* [TR][33] */) {
    const int gcol0 = colBase + tx * 4;
    #pragma unroll
    for (int bt = 0; bt < TR / 32; bt++) { // 4 batches
        const int r0 = bt * 32 + ty;       // rows r0, r0+8, r0+16, r0+24
        const float* base = sim + (size_t)(rowBase + r0) * B + gcol0;

        float4 v[4];
        #pragma unroll
        for (int k = 0; k < 4; k++)        // 4 independent loads, front-batched
            v[k] = *reinterpret_cast<const float4*>(base + (size_t)k * 8 * B);

        if (DIAG) {
            #pragma unroll
            for (int k = 0; k < 4; k++) {
                const int gr = rowBase + r0 + k * 8;
                if (gr == gcol0 + 0) { g_diag[gr] = v[k].x; v[k].x = NEG_INF; }
                if (gr == gcol0 + 1) { g_diag[gr] = v[k].y; v[k].y = NEG_INF; }
                if (gr == gcol0 + 2) { g_diag[gr] = v[k].z; v[k].z = NEG_INF; }
                if (gr == gcol0 + 3) { g_diag[gr] = v[k].w; v[k].w = NEG_INF; }
            }
        }

        #pragma unroll
        for (int k = 0; k < 4; k++) {
            cm[0] = fmaxf(cm[0], v[k].x);
            cm[1] = fmaxf(cm[1], v[k].y);
            cm[2] = fmaxf(cm[2], v[k].z);
            cm[3] = fmaxf(cm[3], v[k].w);
            // per-lane row partial -> shared; no redux, no shuffle, no branch
            s_part[(r0 + k * 8) * 33 + tx] =
                fmaxf(fmaxf(v[k].x, v[k].y), fmaxf(v[k].z, v[k].w));
        }
    }
}

__global__ void __launch_bounds__(256, 8) wtl_k1(const float* __restrict__ sim) {
    const int tx = threadIdx.x;            // 0..31
    const int ty = threadIdx.y;            // 0..7
    const int tid = ty * 32 + tx;
    const int colBase = blockIdx.x * TC;
    const int rowBase = blockIdx.y * TR;

    __shared__ float s_part[TR * 33];      // 16.9 KB, padded: conflict-free
    __shared__ float s_col[8][TC];         // 4 KB

    float cm[4];
    cm[0] = cm[1] = cm[2] = cm[3] = NEG_INF;

    // Diagonal intersects this tile iff bx == by (TC == TR == 128).
    if (blockIdx.x == blockIdx.y)
        scan_body<true >(sim, rowBase, colBase, tx, ty, cm, s_part);
    else
        scan_body<false>(sim, rowBase, colBase, tx, ty, cm, s_part);

    *reinterpret_cast<float4*>(&s_col[ty][tx * 4]) =
        make_float4(cm[0], cm[1], cm[2], cm[3]);
    __syncthreads();

    // Drain: threads 0-127 fold one row each (32 conflict-free LDS),
    // threads 128-255 fold one column each. Both halves run concurrently.
    if (tid < TR) {
        float m = s_part[tid * 33 + 0];
        #pragma unroll
        for (int k = 1; k < 32; k++)
            m = fmaxf(m, s_part[tid * 33 + k]);
        atomicMax(&g_rowmax[rowBase + tid], enc2(m));
    } else {
        const int c = tid - TR;            // 0..127
        float m = s_col[0][c];
        #pragma unroll
        for (int s = 1; s < 8; s++) m = fmaxf(m, s_col[s][c]);
        atomicMax(&g_colmax[colBase + c], enc2(m));
    }
}

// ---------------------------------------------------------------------------
// K2: R10's proven finisher, launched with PDL (unchanged from R15/R16).
// ---------------------------------------------------------------------------
__global__ void __launch_bounds__(128) wtl_k2(float* __restrict__ out) {
    cudaGridDependencySynchronize();       // wait for K1, visibility guaranteed

    const int tid = threadIdx.x;
    const int i = blockIdx.x * 128 + tid;

    const float rm  = dec2(g_rowmax[i]);
    const float cx  = dec2(g_colmax[i]);
    const float pos = g_diag[i];

    g_rowmax[i] = 0u;                      // reset for next replay
    g_colmax[i] = 0u;

    const float pos_loss = fmaxf(0.2f * pos * pos - 0.7f * pos + 0.5f, 0.0f);
    float local = 0.0f;
    if (rm + 1.0f > pos)
        local += pos_loss + fmaxf(0.9f * rm * rm - 0.4f * rm + 0.03f, 0.0f);
    if (cx + 1.0f > pos)
        local += pos_loss + fmaxf(0.9f * cx * cx - 0.4f * cx + 0.03f, 0.0f);

    // deterministic fixed-tree block reduction
    __shared__ float s_sum[128];
    s_sum[tid] = local;
    __syncthreads();
    #pragma unroll
    for (int s = 64; s > 0; s >>= 1) {
        if (tid < s) s_sum[tid] += s_sum[tid + s];
        __syncthreads();
    }

    // publish; last-arriving block finishes.
    __shared__ unsigned s_last;
    if (tid == 0) {
        g_blocksum[blockIdx.x] = s_sum[0];
        __threadfence();
        s_last = atomicAdd(&g_done, 1u);
    }
    __syncthreads();
    if (s_last != K2_BLOCKS - 1) return;
    if (tid == 0) __threadfence();         // acquire all block sums
    __syncthreads();

    if (tid < 32) {
        float v = g_blocksum[tid] + g_blocksum[tid + 32];  // 64 sums
        #pragma unroll
        for (int o = 16; o > 0; o >>= 1)
            v += __shfl_xor_sync(0xffffffffu, v, o);
        if (tid == 0) {
            out[0] = v / (float)B;
            g_done = 0u;                   // reset for next replay
        }
    }
}

extern "C" void kernel_launch(void* const* d_in, const int* in_sizes, int n_in,
                              void* d_out, int out_size) {
    const float* sim = (const float*)d_in[0];
    float* out = (float*)d_out;

    dim3 grid1(GX, GY);        // (64, 64)
    dim3 block1(32, 8);
    wtl_k1<<<grid1, block1>>>(sim);

    // K2 with programmatic dependent launch: overlap its launch latency
    // with K1's drain.
    cudaLaunchConfig_t cfg = {};
    cfg.gridDim  = dim3(K2_BLOCKS, 1, 1);
    cfg.blockDim = dim3(128, 1, 1);
    cfg.dynamicSmemBytes = 0;
    cudaLaunchAttribute attrs[1];
    attrs[0].id = cudaLaunchAttributeProgrammaticStreamSerialization;
    attrs[0].val.programmaticStreamSerializationAllowed = 1;
    cfg.attrs = attrs;
    cfg.numAttrs = 1;
    cudaLaunchKernelEx(&cfg, wtl_k2, out);
}